// round 14
// baseline (speedup 1.0000x reference)
#include <cuda_runtime.h>
#include <cstdint>
#include <cstddef>

// ---------------- problem constants ----------------
constexpr int RES7  = 7;
constexpr int NBOX  = 1024;
constexpr int C_IN  = 128;
constexpr int REP   = 896;                  // 128*7
constexpr int MROWS = NBOX * 49;            // 50176
constexpr int KCONV = 896;                  // C_IN*7
constexpr int INSZ  = 43904;                // REP*49
constexpr int DIMX = 80, DIMY = 80, DIMZ = 20;
constexpr float PX_SCALE = 5.0f;            // 20 * 0.25

// ---------------- static scratch ----------------
__device__ float g_A  [(size_t)MROWS * KCONV];   // roi out, packed A
__device__ float g_Y  [(size_t)MROWS * REP];     // conv out (row-major)
__device__ float g_X2 [(size_t)NBOX * INSZ];     // normalized, packed A
__device__ float g_WC [(size_t)REP * KCONV];     // conv_w, packed B
__device__ float g_X3 [(size_t)NBOX * REP];      // relu(fc6), packed A
__device__ float g_H6 [(size_t)NBOX * REP];      // zero-init; self-cleaned
__device__ float g_H7 [(size_t)NBOX * REP];      // zero-init; self-cleaned
__device__ float g_stats[2 * REP];               // zero-init; self-cleaned
__device__ float g_mean[REP];
__device__ float g_rsig[REP];

// ---------------- helpers ----------------
__device__ __forceinline__ uint32_t smem_u32(const void* p) {
    uint32_t a;
    asm("{ .reg .u64 t; cvta.to.shared.u64 t, %1; cvt.u32.u64 %0, t; }" : "=r"(a) : "l"(p));
    return a;
}
__device__ __forceinline__ void cp_async16(uint32_t dst, const void* src) {
    asm volatile("cp.async.cg.shared.global [%0], [%1], 16;" :: "r"(dst), "l"(src) : "memory");
}
#define CP_COMMIT() asm volatile("cp.async.commit_group;" ::: "memory")
#define CP_WAIT1()  asm volatile("cp.async.wait_group 1;" ::: "memory")

__device__ __forceinline__ float to_tf32(float x) {
    uint32_t r;
    asm("cvt.rna.tf32.f32 %0, %1;" : "=r"(r) : "f"(x));
    return __uint_as_float(r);
}
__device__ __forceinline__ uint32_t lds_tf32(uint32_t addr) {
    uint32_t v;
    asm volatile("ld.shared.b32 %0, [%1];" : "=r"(v) : "r"(addr));
    asm("cvt.rna.tf32.f32 %0, %0;" : "+r"(v));
    return v;
}

#define MMA1688(c, a, b)                                                    \
    asm volatile("mma.sync.aligned.m16n8k8.row.col.f32.tf32.tf32.f32 "     \
        "{%0,%1,%2,%3},{%4,%5,%6,%7},{%8,%9},{%0,%1,%2,%3};"                \
        : "+f"((c)[0]), "+f"((c)[1]), "+f"((c)[2]), "+f"((c)[3])            \
        : "r"((a)[0]), "r"((a)[1]), "r"((a)[2]), "r"((a)[3]),               \
          "r"((b)[0]), "r"((b)[1]))

#define LDS128(r0_, r1_, r2_, r3_, addr)                                    \
    asm volatile("ld.shared.v4.b32 {%0,%1,%2,%3}, [%4];"                    \
        : "=r"(r0_), "=r"(r1_), "=r"(r2_), "=r"(r3_) : "r"(addr))

// ---------------- fragment-order packing ----------------
__device__ __forceinline__ size_t a_pack_idx(int m, int k, int nKC) {
    const int mBlk = m >> 7, mr = m & 127;
    const int wr = mr >> 6, mf = (mr >> 4) & 3, h = (mr >> 3) & 1, g = mr & 7;
    const int kc = k >> 5, kk = k & 31;
    const int step = kk >> 3, r = kk & 7, tig = r & 3, q = r >> 2;
    const int unit = ((((step * 4 + mf) * 2 + wr) * 8 + g) * 4 + tig);
    return (((size_t)mBlk * nKC + kc) << 12) + (unit << 2) + (q * 2 + h);
}
__device__ __forceinline__ size_t b_pack_idx(int n, int k, int nKC) {
    const int nBlk = n >> 7, nr = n & 127;
    const int wc = nr >> 5, nf = (nr >> 3) & 3, g = nr & 7;
    const int np = nf >> 1, pf = nf & 1;
    const int kc = k >> 5, kk = k & 31;
    const int step = kk >> 3, r = kk & 7, tig = r & 3, q = r >> 2;
    const int unit = ((((step * 2 + np) * 4 + wc) * 8 + g) * 4 + tig);
    return (((size_t)nBlk * nKC + kc) << 12) + (unit << 2) + (pf * 2 + q);
}

// ================= GEMM 1: packed A + packed B (conv) =================
constexpr int NSTAGE    = 3;
constexpr int STAGE_B   = 32768;
constexpr int GEMM_SMEM = NSTAGE * STAGE_B;       // 98304

__global__ __launch_bounds__(256, 2)
void k_mma_gemm_conv(const float* __restrict__ A, const float* __restrict__ B,
                     float* __restrict__ C, float* __restrict__ stats,
                     int nKC, int ldc, int nChunks) {
    extern __shared__ uint32_t sw[];
    const int tid = threadIdx.x;
    const int wid = tid >> 5, lane = tid & 31;
    const int g = lane >> 2, tig = lane & 3;
    const int wr = wid >> 2, wc = wid & 3;
    const int nBase = blockIdx.x * 128;
    const int mBase = blockIdx.y * 128;
    const int chunk0 = blockIdx.z * nChunks;

    float acc[4][4][4];
    #pragma unroll
    for (int i = 0; i < 4; i++)
        #pragma unroll
        for (int j = 0; j < 4; j++)
            #pragma unroll
            for (int v = 0; v < 4; v++) acc[i][j][v] = 0.f;

    const uint32_t sbase = smem_u32(sw);
    const float* Abase = A + (((size_t)(mBase >> 7) * nKC + chunk0) << 12);
    const float* Bbase = B + (((size_t)(nBase >> 7) * nKC + chunk0) << 12);

    auto issue = [&](int c) {
        if (c < nChunks) {
            const float* Ab = Abase + ((size_t)c << 12);
            const float* Bb = Bbase + ((size_t)c << 12);
            const uint32_t sb = sbase + (c % NSTAGE) * STAGE_B;
            #pragma unroll
            for (int i = 0; i < 8; i++) {
                const int idx = i * 256 + tid;
                const int mat = idx >> 10;
                const int unit = idx & 1023;
                const float* src = (mat ? Bb : Ab) + (unit << 2);
                cp_async16(sb + mat * 16384 + (unit << 4), src);
            }
        }
        CP_COMMIT();
    };

    issue(0); issue(1);

    for (int c = 0; c < nChunks; ++c) {
        CP_WAIT1();                 // stage c complete (<=1 group pending)
        __syncthreads();            // all warps done reading stage (c-1)%3
        issue(c + 2);               // safe: writes stage (c+2)%3 == (c-1)%3
        const uint32_t sA = sbase + (c % NSTAGE) * STAGE_B;
        const uint32_t sB = sA + 16384;

        #pragma unroll
        for (int s0 = 0; s0 < 4; ++s0) {
            const int step = (s0 + wid) & 3;   // warp-staggered (steps commute)
            uint32_t Ar[4][4];
            uint32_t Bw[2][4];
            #pragma unroll
            for (int mf = 0; mf < 4; mf++) {
                const uint32_t addr = sA + (((((step * 4 + mf) * 2 + wr) * 32) + lane) << 4);
                LDS128(Ar[mf][0], Ar[mf][1], Ar[mf][2], Ar[mf][3], addr);
            }
            #pragma unroll
            for (int np = 0; np < 2; np++) {
                const uint32_t addr = sB + (((((step * 2 + np) * 4 + wc) * 32) + lane) << 4);
                LDS128(Bw[np][0], Bw[np][1], Bw[np][2], Bw[np][3], addr);
            }
            #pragma unroll
            for (int mf = 0; mf < 4; mf++) {
                #pragma unroll
                for (int nf = 0; nf < 4; nf++) {
                    uint32_t bfrag[2];
                    bfrag[0] = Bw[nf >> 1][(nf & 1) * 2 + 0];
                    bfrag[1] = Bw[nf >> 1][(nf & 1) * 2 + 1];
                    MMA1688(acc[mf][nf], Ar[mf], bfrag);
                }
            }
        }
    }
    __syncthreads();

    #pragma unroll
    for (int mf = 0; mf < 4; mf++) {
        const int row = mBase + wr * 64 + mf * 16 + g;
        #pragma unroll
        for (int nf = 0; nf < 4; nf++) {
            const int col = nBase + wc * 32 + nf * 8 + tig * 2;
            float* p0 = &C[(size_t)row * ldc + col];
            float* p1 = &C[(size_t)(row + 8) * ldc + col];
            *(float2*)p0 = make_float2(acc[mf][nf][0], acc[mf][nf][1]);
            *(float2*)p1 = make_float2(acc[mf][nf][2], acc[mf][nf][3]);
        }
    }

    // fused per-column sum / sumsq
    {
        __shared__ float sSum[128], sSq[128];
        if (tid < 128) { sSum[tid] = 0.f; sSq[tid] = 0.f; }
        __syncthreads();
        #pragma unroll
        for (int nf = 0; nf < 4; nf++) {
            #pragma unroll
            for (int b = 0; b < 2; b++) {
                float s = 0.f, q = 0.f;
                #pragma unroll
                for (int mf = 0; mf < 4; mf++) {
                    float v0 = acc[mf][nf][b], v1 = acc[mf][nf][b + 2];
                    s += v0 + v1; q += v0 * v0 + v1 * v1;
                }
                s += __shfl_xor_sync(0xffffffffu, s, 16);
                s += __shfl_xor_sync(0xffffffffu, s, 8);
                s += __shfl_xor_sync(0xffffffffu, s, 4);
                q += __shfl_xor_sync(0xffffffffu, q, 16);
                q += __shfl_xor_sync(0xffffffffu, q, 8);
                q += __shfl_xor_sync(0xffffffffu, q, 4);
                if (g == 0) {
                    const int col = wc * 32 + nf * 8 + tig * 2 + b;
                    atomicAdd(&sSum[col], s);
                    atomicAdd(&sSq[col],  q);
                }
            }
        }
        __syncthreads();
        if (tid < 128) {
            atomicAdd(&stats[nBase + tid],       sSum[tid]);
            atomicAdd(&stats[REP + nBase + tid], sSq[tid]);
        }
    }
}

// ====== GEMM 2: packed A, NATURAL-layout B [K, 896] in smem (fc6 / fc7) ======
constexpr int BSTRIDE_W  = 136;
constexpr int BTILE_NB   = 32 * BSTRIDE_W * 4;         // 17408 B
constexpr int STAGE_NB   = 16384 + BTILE_NB;           // 33792 B
constexpr int NB_SMEM    = NSTAGE * STAGE_NB;          // 101376 B

__global__ __launch_bounds__(256, 2)
void k_mma_gemm_nb(const float* __restrict__ A, const float* __restrict__ B,
                   float* __restrict__ C,
                   int nKC, int ldb, int ldc, int nChunks) {
    extern __shared__ uint32_t sw[];
    const int tid = threadIdx.x;
    const int wid = tid >> 5, lane = tid & 31;
    const int g = lane >> 2, tig = lane & 3;
    const int wr = wid >> 2, wc = wid & 3;
    const int nBase = blockIdx.x * 128;
    const int mBase = blockIdx.y * 128;
    const int chunk0 = blockIdx.z * nChunks;

    float acc[4][4][4];
    #pragma unroll
    for (int i = 0; i < 4; i++)
        #pragma unroll
        for (int j = 0; j < 4; j++)
            #pragma unroll
            for (int v = 0; v < 4; v++) acc[i][j][v] = 0.f;

    const uint32_t sbase = smem_u32(sw);
    const float* Abase = A + (((size_t)(mBase >> 7) * nKC + chunk0) << 12);

    auto issue = [&](int c) {
        if (c < nChunks) {
            const float* Ab = Abase + ((size_t)c << 12);
            const float* Bb = B + (size_t)(chunk0 + c) * 32 * ldb + nBase;
            const uint32_t sb = sbase + (c % NSTAGE) * STAGE_NB;
            #pragma unroll
            for (int i = 0; i < 8; i++) {
                const int idx = i * 256 + tid;
                if (idx < 1024) {                          // A: packed units
                    cp_async16(sb + (idx << 4), Ab + (idx << 2));
                } else {                                   // B: 32 rows x 32 units
                    const int unit = idx - 1024;
                    const int row = unit >> 5, col = unit & 31;
                    cp_async16(sb + 16384 + row * (BSTRIDE_W * 4) + (col << 4),
                               Bb + (size_t)row * ldb + (col << 2));
                }
            }
        }
        CP_COMMIT();
    };

    issue(0); issue(1);

    for (int c = 0; c < nChunks; ++c) {
        CP_WAIT1();
        __syncthreads();
        issue(c + 2);
        const uint32_t sA = sbase + (c % NSTAGE) * STAGE_NB;
        const uint32_t sB = sA + 16384;

        #pragma unroll
        for (int s0 = 0; s0 < 4; ++s0) {
            const int step = (s0 + wid) & 3;   // warp-staggered
            uint32_t Ar[4][4];
            #pragma unroll
            for (int mf = 0; mf < 4; mf++) {
                const uint32_t addr = sA + (((((step * 4 + mf) * 2 + wr) * 32) + lane) << 4);
                LDS128(Ar[mf][0], Ar[mf][1], Ar[mf][2], Ar[mf][3], addr);
            }
            const int kw = step * 8 + tig;
            #pragma unroll
            for (int nf = 0; nf < 4; nf++) {
                const int nloc = wc * 32 + nf * 8 + g;
                uint32_t bfrag[2];
                bfrag[0] = lds_tf32(sB + (kw * BSTRIDE_W + nloc) * 4);
                bfrag[1] = lds_tf32(sB + ((kw + 4) * BSTRIDE_W + nloc) * 4);
                #pragma unroll
                for (int mf = 0; mf < 4; mf++)
                    MMA1688(acc[mf][nf], Ar[mf], bfrag);
            }
        }
    }
    __syncthreads();

    #pragma unroll
    for (int mf = 0; mf < 4; mf++) {
        const int row = mBase + wr * 64 + mf * 16 + g;
        #pragma unroll
        for (int nf = 0; nf < 4; nf++) {
            const int col = nBase + wc * 32 + nf * 8 + tig * 2;
            float* p0 = &C[(size_t)row * ldc + col];
            float* p1 = &C[(size_t)(row + 8) * ldc + col];
            atomicAdd(p0,     acc[mf][nf][0]);
            atomicAdd(p0 + 1, acc[mf][nf][1]);
            atomicAdd(p1,     acc[mf][nf][2]);
            atomicAdd(p1 + 1, acc[mf][nf][3]);
        }
    }
}

// ================= glue kernels =================
// tf32 + pack B (conv_w natural [n=r, k])
__global__ void k_cvt(const float* __restrict__ src, float* __restrict__ dst, int total) {
    int i = blockIdx.x * blockDim.x + threadIdx.x;
    if (i < total) {
        const int nn = i / KCONV, k = i % KCONV;
        dst[b_pack_idx(nn, k, 28)] = to_tf32(src[i]);
    }
}

// ROIAlign -> packed A (R8/R12 proven version: grid (49, 1024), 128 threads)
__global__ void k_roi(const float* __restrict__ feat, const float* __restrict__ boxes,
                      const int* __restrict__ bidx, float* __restrict__ A) {
    const int xy = blockIdx.x, n = blockIdx.y, c = threadIdx.x;
    const int qx = xy / RES7, qy = xy % RES7;
    const int m = n * 49 + xy;

    const float x1 = boxes[n*6+0]*PX_SCALE, y1 = boxes[n*6+1]*PX_SCALE,
                z1 = boxes[n*6+2]*PX_SCALE, x2 = boxes[n*6+3]*PX_SCALE,
                y2 = boxes[n*6+4]*PX_SCALE, z2 = boxes[n*6+5]*PX_SCALE;
    const float bx = fmaxf(x2-x1, 1.f) * (1.f/RES7);
    const float by = fmaxf(y2-y1, 1.f) * (1.f/RES7);
    const float bz = fmaxf(z2-z1, 1.f) * (1.f/RES7);
    const float px = x1 + ((float)qx + 0.5f) * bx;
    const float py = y1 + ((float)qy + 0.5f) * by;
    const float fx = floorf(px), lx = px - fx;
    const float fy = floorf(py), ly = py - fy;
    int ix0 = min(max((int)fx, 0), DIMX-1);
    int ix1 = min(max((int)fx + 1, 0), DIMX-1);
    int iy0 = min(max((int)fy, 0), DIMY-1);
    int iy1 = min(max((int)fy + 1, 0), DIMY-1);
    const int b = bidx[n];
    int base[4]; float wxy[4];
    base[0] = ((b*DIMX+ix0)*DIMY+iy0)*DIMZ; wxy[0] = (1.f-lx)*(1.f-ly);
    base[1] = ((b*DIMX+ix0)*DIMY+iy1)*DIMZ; wxy[1] = (1.f-lx)*ly;
    base[2] = ((b*DIMX+ix1)*DIMY+iy0)*DIMZ; wxy[2] = lx*(1.f-ly);
    base[3] = ((b*DIMX+ix1)*DIMY+iy1)*DIMZ; wxy[3] = lx*ly;

    #pragma unroll
    for (int z = 0; z < RES7; z++) {
        const float pz = z1 + ((float)z + 0.5f) * bz;
        const float fz = floorf(pz), lz = pz - fz;
        int iz0 = min(max((int)fz, 0), DIMZ-1);
        int iz1 = min(max((int)fz + 1, 0), DIMZ-1);
        float v = 0.f;
        #pragma unroll
        for (int q = 0; q < 4; q++) {
            float f0 = feat[(size_t)(base[q] + iz0) * C_IN + c];
            float f1 = feat[(size_t)(base[q] + iz1) * C_IN + c];
            v += wxy[q] * ((1.f - lz) * f0 + lz * f1);
        }
        A[a_pack_idx(m, c * RES7 + z, 28)] = to_tf32(v);
    }
}

__global__ void k_finalize(float* __restrict__ stats,
                           float* __restrict__ mean, float* __restrict__ rsig) {
    int r = blockIdx.x * blockDim.x + threadIdx.x;
    if (r < REP) {
        const float inv = 1.0f / (float)MROWS;
        float mu = stats[r] * inv;
        float v  = stats[REP + r] * inv - mu * mu;
        mean[r] = mu;
        rsig[r] = rsqrtf(v + 1e-5f);
        stats[r] = 0.f; stats[REP + r] = 0.f;     // self-clean for next replay
    }
}

// normalize + relu + pack A: Y[n*49+xy, r] -> X2 packed(m=n, k=r*49+xy), nKC=1372
__global__ __launch_bounds__(256) void k_norm(
    const float* __restrict__ Y, float* __restrict__ X2,
    const float* __restrict__ mean, const float* __restrict__ rsig,
    const float* __restrict__ gamma, const float* __restrict__ beta) {
    const int n = blockIdx.x;
    __shared__ float tile[49][129];
    __shared__ float sm[128], sr[128], sg[128], sb[128];
    for (int rc = 0; rc < 7; rc++) {
        const int rbase = rc * 128;
        if (threadIdx.x < 128) {
            int r = rbase + threadIdx.x;
            sm[threadIdx.x] = mean[r];  sr[threadIdx.x] = rsig[r];
            sg[threadIdx.x] = gamma[r]; sb[threadIdx.x] = beta[r];
        }
        for (int idx = threadIdx.x; idx < 49 * 128; idx += 256) {
            int xy = idx >> 7, rr = idx & 127;
            tile[xy][rr] = Y[(size_t)(n * 49 + xy) * REP + rbase + rr];
        }
        __syncthreads();
        for (int o = threadIdx.x; o < 128 * 49; o += 256) {
            int rr = o / 49, xy = o % 49;
            float v = (tile[xy][rr] - sm[rr]) * sr[rr] * sg[rr] + sb[rr];
            X2[a_pack_idx(n, rbase * 49 + o, 1372)] = to_tf32(fmaxf(v, 0.f));
        }
        __syncthreads();
    }
}

// bias + relu + pack A; also self-clean H6
__global__ void k_bias_relu_cvt(float* __restrict__ in, const float* __restrict__ bias,
                                float* __restrict__ dst) {
    int i = blockIdx.x * blockDim.x + threadIdx.x;
    if (i < NBOX * REP) {
        const int m = i / REP, k = i % REP;
        dst[a_pack_idx(m, k, 28)] = to_tf32(fmaxf(in[i] + bias[k], 0.f));
        in[i] = 0.f;
    }
}

// bias + relu -> out; also self-clean H7
__global__ void k_bias_relu(float* __restrict__ in, const float* __restrict__ bias,
                            float* __restrict__ out) {
    int i = blockIdx.x * blockDim.x + threadIdx.x;
    if (i < NBOX * REP) {
        out[i] = fmaxf(in[i] + bias[i % REP], 0.f);
        in[i] = 0.f;
    }
}

// ---------------- launch ----------------
extern "C" void kernel_launch(void* const* d_in, const int* in_sizes, int n_in,
                              void* d_out, int out_size) {
    const float* feat   = (const float*)d_in[0];
    const float* boxes  = (const float*)d_in[1];
    const float* conv_w = (const float*)d_in[2];
    // conv_b (d_in[3]) cancels in the mean subtraction
    const float* gamma  = (const float*)d_in[4];
    const float* beta   = (const float*)d_in[5];
    const float* fc6_w  = (const float*)d_in[6];
    const float* fc6_b  = (const float*)d_in[7];
    const float* fc7_w  = (const float*)d_in[8];
    const float* fc7_b  = (const float*)d_in[9];
    const int*   bidx   = (const int*)d_in[10];
    float* out = (float*)d_out;

    auto sym = [](const void* s) { void* p = nullptr; cudaGetSymbolAddress(&p, s); return p; };
    float* A    = (float*)sym(g_A);
    float* Y    = (float*)sym(g_Y);
    float* X2   = (float*)sym(g_X2);
    float* WC   = (float*)sym(g_WC);
    float* X3   = (float*)sym(g_X3);
    float* H6   = (float*)sym(g_H6);
    float* H7   = (float*)sym(g_H7);
    float* STATS= (float*)sym(g_stats);
    float* MEAN = (float*)sym(g_mean);
    float* RSIG = (float*)sym(g_rsig);

    cudaFuncSetAttribute(k_mma_gemm_conv, cudaFuncAttributeMaxDynamicSharedMemorySize, GEMM_SMEM);
    cudaFuncSetAttribute(k_mma_gemm_nb,   cudaFuncAttributeMaxDynamicSharedMemorySize, NB_SMEM);

    // #1 conv weights (tf32 + pack)
    k_cvt<<<(REP * KCONV + 255) / 256, 256>>>(conv_w, WC, REP * KCONV);
    // #2 ROIAlign -> packed A (R12 scalar form)
    k_roi<<<dim3(49, NBOX), 128>>>(feat, boxes, bidx, A);
    // #3 warmup finalize (keeps conv GEMM at ncu anchor #4; stats are zero)
    k_finalize<<<7, 128>>>(STATS, MEAN, RSIG);
    // #4 conv einsum GEMM + fused stats (ncu anchor)
    k_mma_gemm_conv<<<dim3(7, 392, 1), 256, GEMM_SMEM>>>(
        A, WC, Y, STATS, 28, REP, 28);
    // #5 mean / rsig (+ stats self-clean)
    k_finalize<<<7, 128>>>(STATS, MEAN, RSIG);
    // #6 normalize + relu -> X2 packed
    k_norm<<<NBOX, 256>>>(Y, X2, MEAN, RSIG, gamma, beta);
    // #7 fc6 GEMM, split-K 14, B = fc6_w natural in smem
    k_mma_gemm_nb<<<dim3(7, 8, 14), 256, NB_SMEM>>>(
        X2, fc6_w, H6, 1372, REP, REP, 98);
    // #8 bias+relu -> X3 packed (+ H6 self-clean)
    k_bias_relu_cvt<<<3584, 256>>>(H6, fc6_b, X3);
    // #9 fc7 GEMM, split-K 4, B = fc7_w natural in smem
    k_mma_gemm_nb<<<dim3(7, 8, 4), 256, NB_SMEM>>>(
        X3, fc7_w, H7, 28, REP, REP, 7);
    // #10 bias + relu -> out (+ H7 self-clean)
    k_bias_relu<<<3584, 256>>>(H7, fc7_b, out);
}

// round 15
// speedup vs baseline: 1.5389x; 1.5389x over previous
#include <cuda_runtime.h>
#include <cstdint>
#include <cstddef>

// ---------------- problem constants ----------------
constexpr int RES7  = 7;
constexpr int NBOX  = 1024;
constexpr int C_IN  = 128;
constexpr int REP   = 896;                  // 128*7
constexpr int MROWS = NBOX * 49;            // 50176
constexpr int KCONV = 896;                  // C_IN*7
constexpr int INSZ  = 43904;                // REP*49
constexpr int DIMX = 80, DIMY = 80, DIMZ = 20;
constexpr float PX_SCALE = 5.0f;            // 20 * 0.25

// ---------------- static scratch ----------------
__device__ float g_A  [(size_t)MROWS * KCONV];   // roi out, packed A
__device__ float g_Y  [(size_t)MROWS * REP];     // conv out (row-major)
__device__ float g_X2 [(size_t)NBOX * INSZ];     // normalized, packed A
__device__ float g_WC [(size_t)REP * KCONV];     // conv_w, packed B
__device__ float g_X3 [(size_t)NBOX * REP];      // relu(fc6), packed A
__device__ float g_H6 [(size_t)NBOX * REP];      // zero-init; self-cleaned
__device__ float g_H7 [(size_t)NBOX * REP];      // zero-init; self-cleaned
__device__ float g_stats[2 * REP];               // zero-init; self-cleaned
__device__ float g_mean[REP];
__device__ float g_rsig[REP];

// ---------------- helpers ----------------
__device__ __forceinline__ uint32_t smem_u32(const void* p) {
    uint32_t a;
    asm("{ .reg .u64 t; cvta.to.shared.u64 t, %1; cvt.u32.u64 %0, t; }" : "=r"(a) : "l"(p));
    return a;
}
__device__ __forceinline__ void cp_async16(uint32_t dst, const void* src) {
    asm volatile("cp.async.cg.shared.global [%0], [%1], 16;" :: "r"(dst), "l"(src) : "memory");
}
#define CP_COMMIT() asm volatile("cp.async.commit_group;" ::: "memory")
#define CP_WAIT2()  asm volatile("cp.async.wait_group 2;" ::: "memory")

__device__ __forceinline__ float to_tf32(float x) {
    uint32_t r;
    asm("cvt.rna.tf32.f32 %0, %1;" : "=r"(r) : "f"(x));
    return __uint_as_float(r);
}
__device__ __forceinline__ uint32_t lds_tf32(uint32_t addr) {
    uint32_t v;
    asm volatile("ld.shared.b32 %0, [%1];" : "=r"(v) : "r"(addr));
    asm("cvt.rna.tf32.f32 %0, %0;" : "+r"(v));
    return v;
}

#define MMA1688(c, a, b)                                                    \
    asm volatile("mma.sync.aligned.m16n8k8.row.col.f32.tf32.tf32.f32 "     \
        "{%0,%1,%2,%3},{%4,%5,%6,%7},{%8,%9},{%0,%1,%2,%3};"                \
        : "+f"((c)[0]), "+f"((c)[1]), "+f"((c)[2]), "+f"((c)[3])            \
        : "r"((a)[0]), "r"((a)[1]), "r"((a)[2]), "r"((a)[3]),               \
          "r"((b)[0]), "r"((b)[1]))

#define LDS128(r0_, r1_, r2_, r3_, addr)                                    \
    asm volatile("ld.shared.v4.b32 {%0,%1,%2,%3}, [%4];"                    \
        : "=r"(r0_), "=r"(r1_), "=r"(r2_), "=r"(r3_) : "r"(addr))

// ---------------- fragment-order packing ----------------
__device__ __forceinline__ size_t a_pack_idx(int m, int k, int nKC) {
    const int mBlk = m >> 7, mr = m & 127;
    const int wr = mr >> 6, mf = (mr >> 4) & 3, h = (mr >> 3) & 1, g = mr & 7;
    const int kc = k >> 5, kk = k & 31;
    const int step = kk >> 3, r = kk & 7, tig = r & 3, q = r >> 2;
    const int unit = ((((step * 4 + mf) * 2 + wr) * 8 + g) * 4 + tig);
    return (((size_t)mBlk * nKC + kc) << 12) + (unit << 2) + (q * 2 + h);
}
__device__ __forceinline__ size_t b_pack_idx(int n, int k, int nKC) {
    const int nBlk = n >> 7, nr = n & 127;
    const int wc = nr >> 5, nf = (nr >> 3) & 3, g = nr & 7;
    const int np = nf >> 1, pf = nf & 1;
    const int kc = k >> 5, kk = k & 31;
    const int step = kk >> 3, r = kk & 7, tig = r & 3, q = r >> 2;
    const int unit = ((((step * 2 + np) * 4 + wc) * 8 + g) * 4 + tig);
    return (((size_t)nBlk * nKC + kc) << 12) + (unit << 2) + (pf * 2 + q);
}

// ================= GEMM 1: packed A + packed B (conv) =================
constexpr int NSTAGE    = 3;
constexpr int STAGE_B   = 32768;
constexpr int GEMM_SMEM = NSTAGE * STAGE_B;       // 98304

__global__ __launch_bounds__(256, 2)
void k_mma_gemm_conv(const float* __restrict__ A, const float* __restrict__ B,
                     float* __restrict__ C, float* __restrict__ stats,
                     int nKC, int ldc, int nChunks) {
    extern __shared__ uint32_t sw[];
    const int tid = threadIdx.x;
    const int wid = tid >> 5, lane = tid & 31;
    const int g = lane >> 2, tig = lane & 3;
    const int wr = wid >> 2, wc = wid & 3;
    const int nBase = blockIdx.x * 128;
    const int mBase = blockIdx.y * 128;
    const int chunk0 = blockIdx.z * nChunks;

    float acc[4][4][4];
    #pragma unroll
    for (int i = 0; i < 4; i++)
        #pragma unroll
        for (int j = 0; j < 4; j++)
            #pragma unroll
            for (int v = 0; v < 4; v++) acc[i][j][v] = 0.f;

    const uint32_t sbase = smem_u32(sw);
    const float* Abase = A + (((size_t)(mBase >> 7) * nKC + chunk0) << 12);
    const float* Bbase = B + (((size_t)(nBase >> 7) * nKC + chunk0) << 12);

    auto issue = [&](int c) {
        if (c < nChunks) {
            const float* Ab = Abase + ((size_t)c << 12);
            const float* Bb = Bbase + ((size_t)c << 12);
            const uint32_t sb = sbase + (c % NSTAGE) * STAGE_B;
            #pragma unroll
            for (int i = 0; i < 8; i++) {
                const int idx = i * 256 + tid;
                const int mat = idx >> 10;
                const int unit = idx & 1023;
                const float* src = (mat ? Bb : Ab) + (unit << 2);
                cp_async16(sb + mat * 16384 + (unit << 4), src);
            }
        }
        CP_COMMIT();
    };

    issue(0); issue(1); issue(2);

    for (int c = 0; c < nChunks; ++c) {
        CP_WAIT2();
        __syncthreads();
        const uint32_t sA = sbase + (c % NSTAGE) * STAGE_B;
        const uint32_t sB = sA + 16384;

        #pragma unroll
        for (int step = 0; step < 4; ++step) {
            uint32_t Ar[4][4];
            uint32_t Bw[2][4];
            #pragma unroll
            for (int mf = 0; mf < 4; mf++) {
                const uint32_t addr = sA + (((((step * 4 + mf) * 2 + wr) * 32) + lane) << 4);
                LDS128(Ar[mf][0], Ar[mf][1], Ar[mf][2], Ar[mf][3], addr);
            }
            #pragma unroll
            for (int np = 0; np < 2; np++) {
                const uint32_t addr = sB + (((((step * 2 + np) * 4 + wc) * 32) + lane) << 4);
                LDS128(Bw[np][0], Bw[np][1], Bw[np][2], Bw[np][3], addr);
            }
            #pragma unroll
            for (int mf = 0; mf < 4; mf++) {
                #pragma unroll
                for (int nf = 0; nf < 4; nf++) {
                    uint32_t bfrag[2];
                    bfrag[0] = Bw[nf >> 1][(nf & 1) * 2 + 0];
                    bfrag[1] = Bw[nf >> 1][(nf & 1) * 2 + 1];
                    MMA1688(acc[mf][nf], Ar[mf], bfrag);
                }
            }
        }
        __syncthreads();
        issue(c + NSTAGE);
    }

    #pragma unroll
    for (int mf = 0; mf < 4; mf++) {
        const int row = mBase + wr * 64 + mf * 16 + g;
        #pragma unroll
        for (int nf = 0; nf < 4; nf++) {
            const int col = nBase + wc * 32 + nf * 8 + tig * 2;
            float* p0 = &C[(size_t)row * ldc + col];
            float* p1 = &C[(size_t)(row + 8) * ldc + col];
            *(float2*)p0 = make_float2(acc[mf][nf][0], acc[mf][nf][1]);
            *(float2*)p1 = make_float2(acc[mf][nf][2], acc[mf][nf][3]);
        }
    }

    // fused per-column sum / sumsq
    {
        __shared__ float sSum[128], sSq[128];
        if (tid < 128) { sSum[tid] = 0.f; sSq[tid] = 0.f; }
        __syncthreads();
        #pragma unroll
        for (int nf = 0; nf < 4; nf++) {
            #pragma unroll
            for (int b = 0; b < 2; b++) {
                float s = 0.f, q = 0.f;
                #pragma unroll
                for (int mf = 0; mf < 4; mf++) {
                    float v0 = acc[mf][nf][b], v1 = acc[mf][nf][b + 2];
                    s += v0 + v1; q += v0 * v0 + v1 * v1;
                }
                s += __shfl_xor_sync(0xffffffffu, s, 16);
                s += __shfl_xor_sync(0xffffffffu, s, 8);
                s += __shfl_xor_sync(0xffffffffu, s, 4);
                q += __shfl_xor_sync(0xffffffffu, q, 16);
                q += __shfl_xor_sync(0xffffffffu, q, 8);
                q += __shfl_xor_sync(0xffffffffu, q, 4);
                if (g == 0) {
                    const int col = wc * 32 + nf * 8 + tig * 2 + b;
                    atomicAdd(&sSum[col], s);
                    atomicAdd(&sSq[col],  q);
                }
            }
        }
        __syncthreads();
        if (tid < 128) {
            atomicAdd(&stats[nBase + tid],       sSum[tid]);
            atomicAdd(&stats[REP + nBase + tid], sSq[tid]);
        }
    }
}

// ====== GEMM 2: packed A, NATURAL-layout B [K, 896] in smem (fc6 / fc7) ======
constexpr int BSTRIDE_W  = 136;
constexpr int BTILE_NB   = 32 * BSTRIDE_W * 4;         // 17408 B
constexpr int STAGE_NB   = 16384 + BTILE_NB;           // 33792 B
constexpr int NB_SMEM    = NSTAGE * STAGE_NB;          // 101376 B

__global__ __launch_bounds__(256, 2)
void k_mma_gemm_nb(const float* __restrict__ A, const float* __restrict__ B,
                   float* __restrict__ C,
                   int nKC, int ldb, int ldc, int nChunks) {
    extern __shared__ uint32_t sw[];
    const int tid = threadIdx.x;
    const int wid = tid >> 5, lane = tid & 31;
    const int g = lane >> 2, tig = lane & 3;
    const int wr = wid >> 2, wc = wid & 3;
    const int nBase = blockIdx.x * 128;
    const int mBase = blockIdx.y * 128;
    const int chunk0 = blockIdx.z * nChunks;

    float acc[4][4][4];
    #pragma unroll
    for (int i = 0; i < 4; i++)
        #pragma unroll
        for (int j = 0; j < 4; j++)
            #pragma unroll
            for (int v = 0; v < 4; v++) acc[i][j][v] = 0.f;

    const uint32_t sbase = smem_u32(sw);
    const float* Abase = A + (((size_t)(mBase >> 7) * nKC + chunk0) << 12);

    auto issue = [&](int c) {
        if (c < nChunks) {
            const float* Ab = Abase + ((size_t)c << 12);
            const float* Bb = B + (size_t)(chunk0 + c) * 32 * ldb + nBase;
            const uint32_t sb = sbase + (c % NSTAGE) * STAGE_NB;
            #pragma unroll
            for (int i = 0; i < 8; i++) {
                const int idx = i * 256 + tid;
                if (idx < 1024) {                          // A: packed units
                    cp_async16(sb + (idx << 4), Ab + (idx << 2));
                } else {                                   // B: 32 rows x 32 units
                    const int unit = idx - 1024;
                    const int row = unit >> 5, col = unit & 31;
                    cp_async16(sb + 16384 + row * (BSTRIDE_W * 4) + (col << 4),
                               Bb + (size_t)row * ldb + (col << 2));
                }
            }
        }
        CP_COMMIT();
    };

    issue(0); issue(1); issue(2);

    for (int c = 0; c < nChunks; ++c) {
        CP_WAIT2();
        __syncthreads();
        const uint32_t sA = sbase + (c % NSTAGE) * STAGE_NB;
        const uint32_t sB = sA + 16384;

        #pragma unroll
        for (int step = 0; step < 4; ++step) {
            uint32_t Ar[4][4];
            #pragma unroll
            for (int mf = 0; mf < 4; mf++) {
                const uint32_t addr = sA + (((((step * 4 + mf) * 2 + wr) * 32) + lane) << 4);
                LDS128(Ar[mf][0], Ar[mf][1], Ar[mf][2], Ar[mf][3], addr);
            }
            const int kw = step * 8 + tig;
            #pragma unroll
            for (int nf = 0; nf < 4; nf++) {
                const int nloc = wc * 32 + nf * 8 + g;
                uint32_t bfrag[2];
                bfrag[0] = lds_tf32(sB + (kw * BSTRIDE_W + nloc) * 4);
                bfrag[1] = lds_tf32(sB + ((kw + 4) * BSTRIDE_W + nloc) * 4);
                #pragma unroll
                for (int mf = 0; mf < 4; mf++)
                    MMA1688(acc[mf][nf], Ar[mf], bfrag);
            }
        }
        __syncthreads();
        issue(c + NSTAGE);
    }

    #pragma unroll
    for (int mf = 0; mf < 4; mf++) {
        const int row = mBase + wr * 64 + mf * 16 + g;
        #pragma unroll
        for (int nf = 0; nf < 4; nf++) {
            const int col = nBase + wc * 32 + nf * 8 + tig * 2;
            float* p0 = &C[(size_t)row * ldc + col];
            float* p1 = &C[(size_t)(row + 8) * ldc + col];
            atomicAdd(p0,     acc[mf][nf][0]);
            atomicAdd(p0 + 1, acc[mf][nf][1]);
            atomicAdd(p1,     acc[mf][nf][2]);
            atomicAdd(p1 + 1, acc[mf][nf][3]);
        }
    }
}

// ================= glue kernels =================
// tf32 + pack B (conv_w natural [n=r, k])
__global__ void k_cvt(const float* __restrict__ src, float* __restrict__ dst, int total) {
    int i = blockIdx.x * blockDim.x + threadIdx.x;
    if (i < total) {
        const int nn = i / KCONV, k = i % KCONV;
        dst[b_pack_idx(nn, k, 28)] = to_tf32(src[i]);
    }
}

// ROIAlign -> packed A (proven version: grid (49, 1024), 128 threads)
__global__ void k_roi(const float* __restrict__ feat, const float* __restrict__ boxes,
                      const int* __restrict__ bidx, float* __restrict__ A) {
    const int xy = blockIdx.x, n = blockIdx.y, c = threadIdx.x;
    const int qx = xy / RES7, qy = xy % RES7;
    const int m = n * 49 + xy;

    const float x1 = boxes[n*6+0]*PX_SCALE, y1 = boxes[n*6+1]*PX_SCALE,
                z1 = boxes[n*6+2]*PX_SCALE, x2 = boxes[n*6+3]*PX_SCALE,
                y2 = boxes[n*6+4]*PX_SCALE, z2 = boxes[n*6+5]*PX_SCALE;
    const float bx = fmaxf(x2-x1, 1.f) * (1.f/RES7);
    const float by = fmaxf(y2-y1, 1.f) * (1.f/RES7);
    const float bz = fmaxf(z2-z1, 1.f) * (1.f/RES7);
    const float px = x1 + ((float)qx + 0.5f) * bx;
    const float py = y1 + ((float)qy + 0.5f) * by;
    const float fx = floorf(px), lx = px - fx;
    const float fy = floorf(py), ly = py - fy;
    int ix0 = min(max((int)fx, 0), DIMX-1);
    int ix1 = min(max((int)fx + 1, 0), DIMX-1);
    int iy0 = min(max((int)fy, 0), DIMY-1);
    int iy1 = min(max((int)fy + 1, 0), DIMY-1);
    const int b = bidx[n];
    int base[4]; float wxy[4];
    base[0] = ((b*DIMX+ix0)*DIMY+iy0)*DIMZ; wxy[0] = (1.f-lx)*(1.f-ly);
    base[1] = ((b*DIMX+ix0)*DIMY+iy1)*DIMZ; wxy[1] = (1.f-lx)*ly;
    base[2] = ((b*DIMX+ix1)*DIMY+iy0)*DIMZ; wxy[2] = lx*(1.f-ly);
    base[3] = ((b*DIMX+ix1)*DIMY+iy1)*DIMZ; wxy[3] = lx*ly;

    #pragma unroll
    for (int z = 0; z < RES7; z++) {
        const float pz = z1 + ((float)z + 0.5f) * bz;
        const float fz = floorf(pz), lz = pz - fz;
        int iz0 = min(max((int)fz, 0), DIMZ-1);
        int iz1 = min(max((int)fz + 1, 0), DIMZ-1);
        float v = 0.f;
        #pragma unroll
        for (int q = 0; q < 4; q++) {
            float f0 = feat[(size_t)(base[q] + iz0) * C_IN + c];
            float f1 = feat[(size_t)(base[q] + iz1) * C_IN + c];
            v += wxy[q] * ((1.f - lz) * f0 + lz * f1);
        }
        A[a_pack_idx(m, c * RES7 + z, 28)] = to_tf32(v);
    }
}

__global__ void k_finalize(float* __restrict__ stats,
                           float* __restrict__ mean, float* __restrict__ rsig) {
    int r = blockIdx.x * blockDim.x + threadIdx.x;
    if (r < REP) {
        const float inv = 1.0f / (float)MROWS;
        float mu = stats[r] * inv;
        float v  = stats[REP + r] * inv - mu * mu;
        mean[r] = mu;
        rsig[r] = rsqrtf(v + 1e-5f);
        stats[r] = 0.f; stats[REP + r] = 0.f;     // self-clean for next replay
    }
}

// normalize + relu + pack A: Y[n*49+xy, r] -> X2 packed(m=n, k=r*49+xy), nKC=1372
__global__ __launch_bounds__(256) void k_norm(
    const float* __restrict__ Y, float* __restrict__ X2,
    const float* __restrict__ mean, const float* __restrict__ rsig,
    const float* __restrict__ gamma, const float* __restrict__ beta) {
    const int n = blockIdx.x;
    __shared__ float tile[49][129];
    __shared__ float sm[128], sr[128], sg[128], sb[128];
    for (int rc = 0; rc < 7; rc++) {
        const int rbase = rc * 128;
        if (threadIdx.x < 128) {
            int r = rbase + threadIdx.x;
            sm[threadIdx.x] = mean[r];  sr[threadIdx.x] = rsig[r];
            sg[threadIdx.x] = gamma[r]; sb[threadIdx.x] = beta[r];
        }
        for (int idx = threadIdx.x; idx < 49 * 128; idx += 256) {
            int xy = idx >> 7, rr = idx & 127;
            tile[xy][rr] = Y[(size_t)(n * 49 + xy) * REP + rbase + rr];
        }
        __syncthreads();
        for (int o = threadIdx.x; o < 128 * 49; o += 256) {
            int rr = o / 49, xy = o % 49;
            float v = (tile[xy][rr] - sm[rr]) * sr[rr] * sg[rr] + sb[rr];
            X2[a_pack_idx(n, rbase * 49 + o, 1372)] = to_tf32(fmaxf(v, 0.f));
        }
        __syncthreads();
    }
}

// bias + relu + pack A; also self-clean H6
__global__ void k_bias_relu_cvt(float* __restrict__ in, const float* __restrict__ bias,
                                float* __restrict__ dst) {
    int i = blockIdx.x * blockDim.x + threadIdx.x;
    if (i < NBOX * REP) {
        const int m = i / REP, k = i % REP;
        dst[a_pack_idx(m, k, 28)] = to_tf32(fmaxf(in[i] + bias[k], 0.f));
        in[i] = 0.f;
    }
}

// bias + relu -> out; also self-clean H7
__global__ void k_bias_relu(float* __restrict__ in, const float* __restrict__ bias,
                            float* __restrict__ out) {
    int i = blockIdx.x * blockDim.x + threadIdx.x;
    if (i < NBOX * REP) {
        out[i] = fmaxf(in[i] + bias[i % REP], 0.f);
        in[i] = 0.f;
    }
}

// ---------------- launch ----------------
extern "C" void kernel_launch(void* const* d_in, const int* in_sizes, int n_in,
                              void* d_out, int out_size) {
    const float* feat   = (const float*)d_in[0];
    const float* boxes  = (const float*)d_in[1];
    const float* conv_w = (const float*)d_in[2];
    // conv_b (d_in[3]) cancels in the mean subtraction
    const float* gamma  = (const float*)d_in[4];
    const float* beta   = (const float*)d_in[5];
    const float* fc6_w  = (const float*)d_in[6];
    const float* fc6_b  = (const float*)d_in[7];
    const float* fc7_w  = (const float*)d_in[8];
    const float* fc7_b  = (const float*)d_in[9];
    const int*   bidx   = (const int*)d_in[10];
    float* out = (float*)d_out;

    auto sym = [](const void* s) { void* p = nullptr; cudaGetSymbolAddress(&p, s); return p; };
    float* A    = (float*)sym(g_A);
    float* Y    = (float*)sym(g_Y);
    float* X2   = (float*)sym(g_X2);
    float* WC   = (float*)sym(g_WC);
    float* X3   = (float*)sym(g_X3);
    float* H6   = (float*)sym(g_H6);
    float* H7   = (float*)sym(g_H7);
    float* STATS= (float*)sym(g_stats);
    float* MEAN = (float*)sym(g_mean);
    float* RSIG = (float*)sym(g_rsig);

    cudaFuncSetAttribute(k_mma_gemm_conv, cudaFuncAttributeMaxDynamicSharedMemorySize, GEMM_SMEM);
    cudaFuncSetAttribute(k_mma_gemm_nb,   cudaFuncAttributeMaxDynamicSharedMemorySize, NB_SMEM);

    // #1 conv weights (tf32 + pack)
    k_cvt<<<(REP * KCONV + 255) / 256, 256>>>(conv_w, WC, REP * KCONV);
    // #2 ROIAlign -> packed A (scalar form)
    k_roi<<<dim3(49, NBOX), 128>>>(feat, boxes, bidx, A);
    // #3 warmup finalize (keeps conv GEMM at ncu anchor #4; stats are zero)
    k_finalize<<<7, 128>>>(STATS, MEAN, RSIG);
    // #4 conv einsum GEMM + fused stats (ncu anchor)
    k_mma_gemm_conv<<<dim3(7, 392, 1), 256, GEMM_SMEM>>>(
        A, WC, Y, STATS, 28, REP, 28);
    // #5 mean / rsig (+ stats self-clean)
    k_finalize<<<7, 128>>>(STATS, MEAN, RSIG);
    // #6 normalize + relu -> X2 packed
    k_norm<<<NBOX, 256>>>(Y, X2, MEAN, RSIG, gamma, beta);
    // #7 fc6 GEMM, split-K 14, B = fc6_w natural in smem
    k_mma_gemm_nb<<<dim3(7, 8, 14), 256, NB_SMEM>>>(
        X2, fc6_w, H6, 1372, REP, REP, 98);
    // #8 bias+relu -> X3 packed (+ H6 self-clean)
    k_bias_relu_cvt<<<3584, 256>>>(H6, fc6_b, X3);
    // #9 fc7 GEMM, split-K 4, B = fc7_w natural in smem
    k_mma_gemm_nb<<<dim3(7, 8, 4), 256, NB_SMEM>>>(
        X3, fc7_w, H7, 28, REP, REP, 7);
    // #10 bias + relu -> out (+ H7 self-clean)
    k_bias_relu<<<3584, 256>>>(H7, fc7_b, out);
}

// round 16
// speedup vs baseline: 1.5434x; 1.0029x over previous
#include <cuda_runtime.h>
#include <cstdint>
#include <cstddef>

// ---------------- problem constants ----------------
constexpr int RES7  = 7;
constexpr int NBOX  = 1024;
constexpr int C_IN  = 128;
constexpr int REP   = 896;                  // 128*7
constexpr int MROWS = NBOX * 49;            // 50176
constexpr int KCONV = 896;                  // C_IN*7
constexpr int INSZ  = 43904;                // REP*49
constexpr int DIMX = 80, DIMY = 80, DIMZ = 20;
constexpr float PX_SCALE = 5.0f;            // 20 * 0.25

// ---------------- static scratch ----------------
__device__ float g_A  [(size_t)MROWS * KCONV];   // roi out, packed A
__device__ float g_Y  [(size_t)MROWS * REP];     // conv out (row-major)
__device__ float g_X2 [(size_t)NBOX * INSZ];     // normalized, packed A
__device__ float g_WC [(size_t)REP * KCONV];     // conv_w, packed B
__device__ float g_X3 [(size_t)NBOX * REP];      // relu(fc6), packed A
__device__ float g_H6 [(size_t)NBOX * REP];      // zero-init; self-cleaned
__device__ float g_H7 [(size_t)NBOX * REP];      // zero-init; self-cleaned
__device__ float g_stats[2 * REP];               // zero-init; self-cleaned
__device__ float g_mean[REP];
__device__ float g_rsig[REP];

// ---------------- helpers ----------------
__device__ __forceinline__ uint32_t smem_u32(const void* p) {
    uint32_t a;
    asm("{ .reg .u64 t; cvta.to.shared.u64 t, %1; cvt.u32.u64 %0, t; }" : "=r"(a) : "l"(p));
    return a;
}
__device__ __forceinline__ void cp_async16(uint32_t dst, const void* src) {
    asm volatile("cp.async.cg.shared.global [%0], [%1], 16;" :: "r"(dst), "l"(src) : "memory");
}
#define CP_COMMIT() asm volatile("cp.async.commit_group;" ::: "memory")
#define CP_WAIT2()  asm volatile("cp.async.wait_group 2;" ::: "memory")

__device__ __forceinline__ float to_tf32(float x) {
    uint32_t r;
    asm("cvt.rna.tf32.f32 %0, %1;" : "=r"(r) : "f"(x));
    return __uint_as_float(r);
}
__device__ __forceinline__ uint32_t lds_tf32(uint32_t addr) {
    uint32_t v;
    asm volatile("ld.shared.b32 %0, [%1];" : "=r"(v) : "r"(addr));
    asm("cvt.rna.tf32.f32 %0, %0;" : "+r"(v));
    return v;
}

#define MMA1688(c, a, b)                                                    \
    asm volatile("mma.sync.aligned.m16n8k8.row.col.f32.tf32.tf32.f32 "     \
        "{%0,%1,%2,%3},{%4,%5,%6,%7},{%8,%9},{%0,%1,%2,%3};"                \
        : "+f"((c)[0]), "+f"((c)[1]), "+f"((c)[2]), "+f"((c)[3])            \
        : "r"((a)[0]), "r"((a)[1]), "r"((a)[2]), "r"((a)[3]),               \
          "r"((b)[0]), "r"((b)[1]))

#define LDS128(r0_, r1_, r2_, r3_, addr)                                    \
    asm volatile("ld.shared.v4.b32 {%0,%1,%2,%3}, [%4];"                    \
        : "=r"(r0_), "=r"(r1_), "=r"(r2_), "=r"(r3_) : "r"(addr))

// ---------------- fragment-order packing ----------------
__device__ __forceinline__ size_t a_pack_idx(int m, int k, int nKC) {
    const int mBlk = m >> 7, mr = m & 127;
    const int wr = mr >> 6, mf = (mr >> 4) & 3, h = (mr >> 3) & 1, g = mr & 7;
    const int kc = k >> 5, kk = k & 31;
    const int step = kk >> 3, r = kk & 7, tig = r & 3, q = r >> 2;
    const int unit = ((((step * 4 + mf) * 2 + wr) * 8 + g) * 4 + tig);
    return (((size_t)mBlk * nKC + kc) << 12) + (unit << 2) + (q * 2 + h);
}
__device__ __forceinline__ size_t b_pack_idx(int n, int k, int nKC) {
    const int nBlk = n >> 7, nr = n & 127;
    const int wc = nr >> 5, nf = (nr >> 3) & 3, g = nr & 7;
    const int np = nf >> 1, pf = nf & 1;
    const int kc = k >> 5, kk = k & 31;
    const int step = kk >> 3, r = kk & 7, tig = r & 3, q = r >> 2;
    const int unit = ((((step * 2 + np) * 4 + wc) * 8 + g) * 4 + tig);
    return (((size_t)nBlk * nKC + kc) << 12) + (unit << 2) + (pf * 2 + q);
}

// ================= GEMM 1: packed A + packed B (conv) =================
constexpr int NSTAGE    = 3;
constexpr int STAGE_B   = 32768;
constexpr int GEMM_SMEM = NSTAGE * STAGE_B;       // 98304

__global__ __launch_bounds__(256, 2)
void k_mma_gemm_conv(const float* __restrict__ A, const float* __restrict__ B,
                     float* __restrict__ C, float* __restrict__ stats,
                     int nKC, int ldc, int nChunks) {
    extern __shared__ uint32_t sw[];
    const int tid = threadIdx.x;
    const int wid = tid >> 5, lane = tid & 31;
    const int g = lane >> 2, tig = lane & 3;
    const int wr = wid >> 2, wc = wid & 3;
    const int nBase = blockIdx.x * 128;
    const int mBase = blockIdx.y * 128;
    const int chunk0 = blockIdx.z * nChunks;

    float acc[4][4][4];
    #pragma unroll
    for (int i = 0; i < 4; i++)
        #pragma unroll
        for (int j = 0; j < 4; j++)
            #pragma unroll
            for (int v = 0; v < 4; v++) acc[i][j][v] = 0.f;

    const uint32_t sbase = smem_u32(sw);
    const float* Abase = A + (((size_t)(mBase >> 7) * nKC + chunk0) << 12);
    const float* Bbase = B + (((size_t)(nBase >> 7) * nKC + chunk0) << 12);

    auto issue = [&](int c) {
        if (c < nChunks) {
            const float* Ab = Abase + ((size_t)c << 12);
            const float* Bb = Bbase + ((size_t)c << 12);
            const uint32_t sb = sbase + (c % NSTAGE) * STAGE_B;
            #pragma unroll
            for (int i = 0; i < 8; i++) {
                const int idx = i * 256 + tid;
                const int mat = idx >> 10;
                const int unit = idx & 1023;
                const float* src = (mat ? Bb : Ab) + (unit << 2);
                cp_async16(sb + mat * 16384 + (unit << 4), src);
            }
        }
        CP_COMMIT();
    };

    issue(0); issue(1); issue(2);

    for (int c = 0; c < nChunks; ++c) {
        CP_WAIT2();
        __syncthreads();
        const uint32_t sA = sbase + (c % NSTAGE) * STAGE_B;
        const uint32_t sB = sA + 16384;

        #pragma unroll
        for (int step = 0; step < 4; ++step) {
            uint32_t Ar[4][4];
            uint32_t Bw[2][4];
            #pragma unroll
            for (int mf = 0; mf < 4; mf++) {
                const uint32_t addr = sA + (((((step * 4 + mf) * 2 + wr) * 32) + lane) << 4);
                LDS128(Ar[mf][0], Ar[mf][1], Ar[mf][2], Ar[mf][3], addr);
            }
            #pragma unroll
            for (int np = 0; np < 2; np++) {
                const uint32_t addr = sB + (((((step * 2 + np) * 4 + wc) * 32) + lane) << 4);
                LDS128(Bw[np][0], Bw[np][1], Bw[np][2], Bw[np][3], addr);
            }
            #pragma unroll
            for (int mf = 0; mf < 4; mf++) {
                #pragma unroll
                for (int nf = 0; nf < 4; nf++) {
                    uint32_t bfrag[2];
                    bfrag[0] = Bw[nf >> 1][(nf & 1) * 2 + 0];
                    bfrag[1] = Bw[nf >> 1][(nf & 1) * 2 + 1];
                    MMA1688(acc[mf][nf], Ar[mf], bfrag);
                }
            }
        }
        __syncthreads();
        issue(c + NSTAGE);
    }

    #pragma unroll
    for (int mf = 0; mf < 4; mf++) {
        const int row = mBase + wr * 64 + mf * 16 + g;
        #pragma unroll
        for (int nf = 0; nf < 4; nf++) {
            const int col = nBase + wc * 32 + nf * 8 + tig * 2;
            float* p0 = &C[(size_t)row * ldc + col];
            float* p1 = &C[(size_t)(row + 8) * ldc + col];
            *(float2*)p0 = make_float2(acc[mf][nf][0], acc[mf][nf][1]);
            *(float2*)p1 = make_float2(acc[mf][nf][2], acc[mf][nf][3]);
        }
    }

    // fused per-column sum / sumsq
    {
        __shared__ float sSum[128], sSq[128];
        if (tid < 128) { sSum[tid] = 0.f; sSq[tid] = 0.f; }
        __syncthreads();
        #pragma unroll
        for (int nf = 0; nf < 4; nf++) {
            #pragma unroll
            for (int b = 0; b < 2; b++) {
                float s = 0.f, q = 0.f;
                #pragma unroll
                for (int mf = 0; mf < 4; mf++) {
                    float v0 = acc[mf][nf][b], v1 = acc[mf][nf][b + 2];
                    s += v0 + v1; q += v0 * v0 + v1 * v1;
                }
                s += __shfl_xor_sync(0xffffffffu, s, 16);
                s += __shfl_xor_sync(0xffffffffu, s, 8);
                s += __shfl_xor_sync(0xffffffffu, s, 4);
                q += __shfl_xor_sync(0xffffffffu, q, 16);
                q += __shfl_xor_sync(0xffffffffu, q, 8);
                q += __shfl_xor_sync(0xffffffffu, q, 4);
                if (g == 0) {
                    const int col = wc * 32 + nf * 8 + tig * 2 + b;
                    atomicAdd(&sSum[col], s);
                    atomicAdd(&sSq[col],  q);
                }
            }
        }
        __syncthreads();
        if (tid < 128) {
            atomicAdd(&stats[nBase + tid],       sSum[tid]);
            atomicAdd(&stats[REP + nBase + tid], sSq[tid]);
        }
    }
}

// ====== GEMM 2: packed A, NATURAL-layout B [K, 896] in smem (fc6 / fc7) ======
constexpr int BSTRIDE_W  = 136;
constexpr int BTILE_NB   = 32 * BSTRIDE_W * 4;         // 17408 B
constexpr int STAGE_NB   = 16384 + BTILE_NB;           // 33792 B
constexpr int NB_SMEM    = NSTAGE * STAGE_NB;          // 101376 B

__global__ __launch_bounds__(256, 2)
void k_mma_gemm_nb(const float* __restrict__ A, const float* __restrict__ B,
                   float* __restrict__ C,
                   int nKC, int ldb, int ldc, int nChunks) {
    extern __shared__ uint32_t sw[];
    const int tid = threadIdx.x;
    const int wid = tid >> 5, lane = tid & 31;
    const int g = lane >> 2, tig = lane & 3;
    const int wr = wid >> 2, wc = wid & 3;
    const int nBase = blockIdx.x * 128;
    const int mBase = blockIdx.y * 128;
    const int chunk0 = blockIdx.z * nChunks;

    float acc[4][4][4];
    #pragma unroll
    for (int i = 0; i < 4; i++)
        #pragma unroll
        for (int j = 0; j < 4; j++)
            #pragma unroll
            for (int v = 0; v < 4; v++) acc[i][j][v] = 0.f;

    const uint32_t sbase = smem_u32(sw);
    const float* Abase = A + (((size_t)(mBase >> 7) * nKC + chunk0) << 12);

    auto issue = [&](int c) {
        if (c < nChunks) {
            const float* Ab = Abase + ((size_t)c << 12);
            const float* Bb = B + (size_t)(chunk0 + c) * 32 * ldb + nBase;
            const uint32_t sb = sbase + (c % NSTAGE) * STAGE_NB;
            #pragma unroll
            for (int i = 0; i < 8; i++) {
                const int idx = i * 256 + tid;
                if (idx < 1024) {                          // A: packed units
                    cp_async16(sb + (idx << 4), Ab + (idx << 2));
                } else {                                   // B: 32 rows x 32 units
                    const int unit = idx - 1024;
                    const int row = unit >> 5, col = unit & 31;
                    cp_async16(sb + 16384 + row * (BSTRIDE_W * 4) + (col << 4),
                               Bb + (size_t)row * ldb + (col << 2));
                }
            }
        }
        CP_COMMIT();
    };

    issue(0); issue(1); issue(2);

    for (int c = 0; c < nChunks; ++c) {
        CP_WAIT2();
        __syncthreads();
        const uint32_t sA = sbase + (c % NSTAGE) * STAGE_NB;
        const uint32_t sB = sA + 16384;

        #pragma unroll
        for (int step = 0; step < 4; ++step) {
            uint32_t Ar[4][4];
            #pragma unroll
            for (int mf = 0; mf < 4; mf++) {
                const uint32_t addr = sA + (((((step * 4 + mf) * 2 + wr) * 32) + lane) << 4);
                LDS128(Ar[mf][0], Ar[mf][1], Ar[mf][2], Ar[mf][3], addr);
            }
            const int kw = step * 8 + tig;
            #pragma unroll
            for (int nf = 0; nf < 4; nf++) {
                const int nloc = wc * 32 + nf * 8 + g;
                uint32_t bfrag[2];
                bfrag[0] = lds_tf32(sB + (kw * BSTRIDE_W + nloc) * 4);
                bfrag[1] = lds_tf32(sB + ((kw + 4) * BSTRIDE_W + nloc) * 4);
                #pragma unroll
                for (int mf = 0; mf < 4; mf++)
                    MMA1688(acc[mf][nf], Ar[mf], bfrag);
            }
        }
        __syncthreads();
        issue(c + NSTAGE);
    }

    #pragma unroll
    for (int mf = 0; mf < 4; mf++) {
        const int row = mBase + wr * 64 + mf * 16 + g;
        #pragma unroll
        for (int nf = 0; nf < 4; nf++) {
            const int col = nBase + wc * 32 + nf * 8 + tig * 2;
            float* p0 = &C[(size_t)row * ldc + col];
            float* p1 = &C[(size_t)(row + 8) * ldc + col];
            atomicAdd(p0,     acc[mf][nf][0]);
            atomicAdd(p0 + 1, acc[mf][nf][1]);
            atomicAdd(p1,     acc[mf][nf][2]);
            atomicAdd(p1 + 1, acc[mf][nf][3]);
        }
    }
}

// ================= glue kernels =================
// tf32 + pack B (conv_w natural [n=r, k])
__global__ void k_cvt(const float* __restrict__ src, float* __restrict__ dst, int total) {
    int i = blockIdx.x * blockDim.x + threadIdx.x;
    if (i < total) {
        const int nn = i / KCONV, k = i % KCONV;
        dst[b_pack_idx(nn, k, 28)] = to_tf32(src[i]);
    }
}

// ROIAlign -> packed A (proven version: grid (49, 1024), 128 threads)
__global__ void k_roi(const float* __restrict__ feat, const float* __restrict__ boxes,
                      const int* __restrict__ bidx, float* __restrict__ A) {
    const int xy = blockIdx.x, n = blockIdx.y, c = threadIdx.x;
    const int qx = xy / RES7, qy = xy % RES7;
    const int m = n * 49 + xy;

    const float x1 = boxes[n*6+0]*PX_SCALE, y1 = boxes[n*6+1]*PX_SCALE,
                z1 = boxes[n*6+2]*PX_SCALE, x2 = boxes[n*6+3]*PX_SCALE,
                y2 = boxes[n*6+4]*PX_SCALE, z2 = boxes[n*6+5]*PX_SCALE;
    const float bx = fmaxf(x2-x1, 1.f) * (1.f/RES7);
    const float by = fmaxf(y2-y1, 1.f) * (1.f/RES7);
    const float bz = fmaxf(z2-z1, 1.f) * (1.f/RES7);
    const float px = x1 + ((float)qx + 0.5f) * bx;
    const float py = y1 + ((float)qy + 0.5f) * by;
    const float fx = floorf(px), lx = px - fx;
    const float fy = floorf(py), ly = py - fy;
    int ix0 = min(max((int)fx, 0), DIMX-1);
    int ix1 = min(max((int)fx + 1, 0), DIMX-1);
    int iy0 = min(max((int)fy, 0), DIMY-1);
    int iy1 = min(max((int)fy + 1, 0), DIMY-1);
    const int b = bidx[n];
    int base[4]; float wxy[4];
    base[0] = ((b*DIMX+ix0)*DIMY+iy0)*DIMZ; wxy[0] = (1.f-lx)*(1.f-ly);
    base[1] = ((b*DIMX+ix0)*DIMY+iy1)*DIMZ; wxy[1] = (1.f-lx)*ly;
    base[2] = ((b*DIMX+ix1)*DIMY+iy0)*DIMZ; wxy[2] = lx*(1.f-ly);
    base[3] = ((b*DIMX+ix1)*DIMY+iy1)*DIMZ; wxy[3] = lx*ly;

    #pragma unroll
    for (int z = 0; z < RES7; z++) {
        const float pz = z1 + ((float)z + 0.5f) * bz;
        const float fz = floorf(pz), lz = pz - fz;
        int iz0 = min(max((int)fz, 0), DIMZ-1);
        int iz1 = min(max((int)fz + 1, 0), DIMZ-1);
        float v = 0.f;
        #pragma unroll
        for (int q = 0; q < 4; q++) {
            float f0 = feat[(size_t)(base[q] + iz0) * C_IN + c];
            float f1 = feat[(size_t)(base[q] + iz1) * C_IN + c];
            v += wxy[q] * ((1.f - lz) * f0 + lz * f1);
        }
        A[a_pack_idx(m, c * RES7 + z, 28)] = to_tf32(v);
    }
}

__global__ void k_finalize(float* __restrict__ stats,
                           float* __restrict__ mean, float* __restrict__ rsig) {
    int r = blockIdx.x * blockDim.x + threadIdx.x;
    if (r < REP) {
        const float inv = 1.0f / (float)MROWS;
        float mu = stats[r] * inv;
        float v  = stats[REP + r] * inv - mu * mu;
        mean[r] = mu;
        rsig[r] = rsqrtf(v + 1e-5f);
        stats[r] = 0.f; stats[REP + r] = 0.f;     // self-clean for next replay
    }
}

// normalize + relu + pack A: Y[n*49+xy, r] -> X2 packed(m=n, k=r*49+xy), nKC=1372
__global__ __launch_bounds__(256) void k_norm(
    const float* __restrict__ Y, float* __restrict__ X2,
    const float* __restrict__ mean, const float* __restrict__ rsig,
    const float* __restrict__ gamma, const float* __restrict__ beta) {
    const int n = blockIdx.x;
    __shared__ float tile[49][129];
    __shared__ float sm[128], sr[128], sg[128], sb[128];
    for (int rc = 0; rc < 7; rc++) {
        const int rbase = rc * 128;
        if (threadIdx.x < 128) {
            int r = rbase + threadIdx.x;
            sm[threadIdx.x] = mean[r];  sr[threadIdx.x] = rsig[r];
            sg[threadIdx.x] = gamma[r]; sb[threadIdx.x] = beta[r];
        }
        for (int idx = threadIdx.x; idx < 49 * 128; idx += 256) {
            int xy = idx >> 7, rr = idx & 127;
            tile[xy][rr] = Y[(size_t)(n * 49 + xy) * REP + rbase + rr];
        }
        __syncthreads();
        for (int o = threadIdx.x; o < 128 * 49; o += 256) {
            int rr = o / 49, xy = o % 49;
            float v = (tile[xy][rr] - sm[rr]) * sr[rr] * sg[rr] + sb[rr];
            X2[a_pack_idx(n, rbase * 49 + o, 1372)] = to_tf32(fmaxf(v, 0.f));
        }
        __syncthreads();
    }
}

// bias + relu + pack A (float4 loads); also self-clean H6
__global__ void k_bias_relu_cvt(float* __restrict__ in, const float* __restrict__ bias,
                                float* __restrict__ dst) {
    int j = blockIdx.x * blockDim.x + threadIdx.x;     // float4 index
    if (j < (NBOX * REP) / 4) {
        const int i = j * 4;
        const int m = i / REP, k = i % REP;            // k is 4-aligned, row-local
        float4 v = *(float4*)&in[i];
        float4 bb = *(const float4*)&bias[k];
        dst[a_pack_idx(m, k + 0, 28)] = to_tf32(fmaxf(v.x + bb.x, 0.f));
        dst[a_pack_idx(m, k + 1, 28)] = to_tf32(fmaxf(v.y + bb.y, 0.f));
        dst[a_pack_idx(m, k + 2, 28)] = to_tf32(fmaxf(v.z + bb.z, 0.f));
        dst[a_pack_idx(m, k + 3, 28)] = to_tf32(fmaxf(v.w + bb.w, 0.f));
        *(float4*)&in[i] = make_float4(0.f, 0.f, 0.f, 0.f);
    }
}

// bias + relu -> out (float4); also self-clean H7
__global__ void k_bias_relu(float* __restrict__ in, const float* __restrict__ bias,
                            float* __restrict__ out) {
    int j = blockIdx.x * blockDim.x + threadIdx.x;
    if (j < (NBOX * REP) / 4) {
        const int i = j * 4;
        const int k = i % REP;
        float4 v = *(float4*)&in[i];
        float4 bb = *(const float4*)&bias[k];
        float4 o;
        o.x = fmaxf(v.x + bb.x, 0.f);
        o.y = fmaxf(v.y + bb.y, 0.f);
        o.z = fmaxf(v.z + bb.z, 0.f);
        o.w = fmaxf(v.w + bb.w, 0.f);
        *(float4*)&out[i] = o;
        *(float4*)&in[i] = make_float4(0.f, 0.f, 0.f, 0.f);
    }
}

// ---------------- launch ----------------
extern "C" void kernel_launch(void* const* d_in, const int* in_sizes, int n_in,
                              void* d_out, int out_size) {
    const float* feat   = (const float*)d_in[0];
    const float* boxes  = (const float*)d_in[1];
    const float* conv_w = (const float*)d_in[2];
    // conv_b (d_in[3]) cancels in the mean subtraction
    const float* gamma  = (const float*)d_in[4];
    const float* beta   = (const float*)d_in[5];
    const float* fc6_w  = (const float*)d_in[6];
    const float* fc6_b  = (const float*)d_in[7];
    const float* fc7_w  = (const float*)d_in[8];
    const float* fc7_b  = (const float*)d_in[9];
    const int*   bidx   = (const int*)d_in[10];
    float* out = (float*)d_out;

    auto sym = [](const void* s) { void* p = nullptr; cudaGetSymbolAddress(&p, s); return p; };
    float* A    = (float*)sym(g_A);
    float* Y    = (float*)sym(g_Y);
    float* X2   = (float*)sym(g_X2);
    float* WC   = (float*)sym(g_WC);
    float* X3   = (float*)sym(g_X3);
    float* H6   = (float*)sym(g_H6);
    float* H7   = (float*)sym(g_H7);
    float* STATS= (float*)sym(g_stats);
    float* MEAN = (float*)sym(g_mean);
    float* RSIG = (float*)sym(g_rsig);

    cudaFuncSetAttribute(k_mma_gemm_conv, cudaFuncAttributeMaxDynamicSharedMemorySize, GEMM_SMEM);
    cudaFuncSetAttribute(k_mma_gemm_nb,   cudaFuncAttributeMaxDynamicSharedMemorySize, NB_SMEM);

    // #1 conv weights (tf32 + pack)
    k_cvt<<<(REP * KCONV + 255) / 256, 256>>>(conv_w, WC, REP * KCONV);
    // #2 ROIAlign -> packed A
    k_roi<<<dim3(49, NBOX), 128>>>(feat, boxes, bidx, A);
    // #3 conv einsum GEMM + fused stats
    k_mma_gemm_conv<<<dim3(7, 392, 1), 256, GEMM_SMEM>>>(
        A, WC, Y, STATS, 28, REP, 28);
    // #4 mean / rsig (+ stats self-clean)
    k_finalize<<<7, 128>>>(STATS, MEAN, RSIG);
    // #5 normalize + relu -> X2 packed
    k_norm<<<NBOX, 256>>>(Y, X2, MEAN, RSIG, gamma, beta);
    // #6 fc6 GEMM, split-K 14, B = fc6_w natural in smem
    k_mma_gemm_nb<<<dim3(7, 8, 14), 256, NB_SMEM>>>(
        X2, fc6_w, H6, 1372, REP, REP, 98);
    // #7 bias+relu -> X3 packed (+ H6 self-clean), float4
    k_bias_relu_cvt<<<896, 256>>>(H6, fc6_b, X3);
    // #8 fc7 GEMM, split-K 4, B = fc7_w natural in smem
    k_mma_gemm_nb<<<dim3(7, 8, 4), 256, NB_SMEM>>>(
        X3, fc7_w, H7, 28, REP, REP, 7);
    // #9 bias + relu -> out (+ H7 self-clean), float4
    k_bias_relu<<<896, 256>>>(H7, fc7_b, out);
}

// round 17
// speedup vs baseline: 1.5463x; 1.0019x over previous
#include <cuda_runtime.h>
#include <cstdint>
#include <cstddef>

// ---------------- problem constants ----------------
constexpr int RES7  = 7;
constexpr int NBOX  = 1024;
constexpr int C_IN  = 128;
constexpr int REP   = 896;                  // 128*7
constexpr int MROWS = NBOX * 49;            // 50176
constexpr int KCONV = 896;                  // C_IN*7
constexpr int INSZ  = 43904;                // REP*49
constexpr int DIMX = 80, DIMY = 80, DIMZ = 20;
constexpr float PX_SCALE = 5.0f;            // 20 * 0.25

// ---------------- static scratch ----------------
__device__ float g_A  [(size_t)MROWS * KCONV];   // roi out, packed A
__device__ float g_Y  [(size_t)MROWS * REP];     // conv out (row-major)
__device__ float g_X2 [(size_t)NBOX * INSZ];     // normalized, packed A
__device__ float g_WC [(size_t)REP * KCONV];     // conv_w, packed B
__device__ float g_X3 [(size_t)NBOX * REP];      // relu(fc6), packed A
__device__ float g_H6 [(size_t)NBOX * REP];      // zero-init; self-cleaned
__device__ float g_H7 [(size_t)NBOX * REP];      // zero-init; self-cleaned
__device__ float g_stats[2 * REP];               // zero-init; self-cleaned
__device__ float g_mean[REP];
__device__ float g_rsig[REP];

// ---------------- helpers ----------------
__device__ __forceinline__ uint32_t smem_u32(const void* p) {
    uint32_t a;
    asm("{ .reg .u64 t; cvta.to.shared.u64 t, %1; cvt.u32.u64 %0, t; }" : "=r"(a) : "l"(p));
    return a;
}
__device__ __forceinline__ void cp_async16(uint32_t dst, const void* src) {
    asm volatile("cp.async.cg.shared.global [%0], [%1], 16;" :: "r"(dst), "l"(src) : "memory");
}
#define CP_COMMIT() asm volatile("cp.async.commit_group;" ::: "memory")
#define CP_WAIT2()  asm volatile("cp.async.wait_group 2;" ::: "memory")

__device__ __forceinline__ float to_tf32(float x) {
    uint32_t r;
    asm("cvt.rna.tf32.f32 %0, %1;" : "=r"(r) : "f"(x));
    return __uint_as_float(r);
}
__device__ __forceinline__ uint32_t lds_tf32(uint32_t addr) {
    uint32_t v;
    asm volatile("ld.shared.b32 %0, [%1];" : "=r"(v) : "r"(addr));
    asm("cvt.rna.tf32.f32 %0, %0;" : "+r"(v));
    return v;
}

#define MMA1688(c, a, b)                                                    \
    asm volatile("mma.sync.aligned.m16n8k8.row.col.f32.tf32.tf32.f32 "     \
        "{%0,%1,%2,%3},{%4,%5,%6,%7},{%8,%9},{%0,%1,%2,%3};"                \
        : "+f"((c)[0]), "+f"((c)[1]), "+f"((c)[2]), "+f"((c)[3])            \
        : "r"((a)[0]), "r"((a)[1]), "r"((a)[2]), "r"((a)[3]),               \
          "r"((b)[0]), "r"((b)[1]))

#define LDS128(r0_, r1_, r2_, r3_, addr)                                    \
    asm volatile("ld.shared.v4.b32 {%0,%1,%2,%3}, [%4];"                    \
        : "=r"(r0_), "=r"(r1_), "=r"(r2_), "=r"(r3_) : "r"(addr))

// ---------------- fragment-order packing ----------------
__device__ __forceinline__ size_t a_pack_idx(int m, int k, int nKC) {
    const int mBlk = m >> 7, mr = m & 127;
    const int wr = mr >> 6, mf = (mr >> 4) & 3, h = (mr >> 3) & 1, g = mr & 7;
    const int kc = k >> 5, kk = k & 31;
    const int step = kk >> 3, r = kk & 7, tig = r & 3, q = r >> 2;
    const int unit = ((((step * 4 + mf) * 2 + wr) * 8 + g) * 4 + tig);
    return (((size_t)mBlk * nKC + kc) << 12) + (unit << 2) + (q * 2 + h);
}
__device__ __forceinline__ size_t b_pack_idx(int n, int k, int nKC) {
    const int nBlk = n >> 7, nr = n & 127;
    const int wc = nr >> 5, nf = (nr >> 3) & 3, g = nr & 7;
    const int np = nf >> 1, pf = nf & 1;
    const int kc = k >> 5, kk = k & 31;
    const int step = kk >> 3, r = kk & 7, tig = r & 3, q = r >> 2;
    const int unit = ((((step * 2 + np) * 4 + wc) * 8 + g) * 4 + tig);
    return (((size_t)nBlk * nKC + kc) << 12) + (unit << 2) + (pf * 2 + q);
}

// ================= GEMM 1: packed A + packed B (conv) =================
constexpr int NSTAGE    = 3;
constexpr int STAGE_B   = 32768;
constexpr int GEMM_SMEM = NSTAGE * STAGE_B;       // 98304

__global__ __launch_bounds__(256, 2)
void k_mma_gemm_conv(const float* __restrict__ A, const float* __restrict__ B,
                     float* __restrict__ C, float* __restrict__ stats,
                     int nKC, int ldc, int nChunks) {
    extern __shared__ uint32_t sw[];
    const int tid = threadIdx.x;
    const int wid = tid >> 5, lane = tid & 31;
    const int g = lane >> 2, tig = lane & 3;
    const int wr = wid >> 2, wc = wid & 3;
    const int nBase = blockIdx.x * 128;
    const int mBase = blockIdx.y * 128;
    const int chunk0 = blockIdx.z * nChunks;

    float acc[4][4][4];
    #pragma unroll
    for (int i = 0; i < 4; i++)
        #pragma unroll
        for (int j = 0; j < 4; j++)
            #pragma unroll
            for (int v = 0; v < 4; v++) acc[i][j][v] = 0.f;

    const uint32_t sbase = smem_u32(sw);
    const float* Abase = A + (((size_t)(mBase >> 7) * nKC + chunk0) << 12);
    const float* Bbase = B + (((size_t)(nBase >> 7) * nKC + chunk0) << 12);

    auto issue = [&](int c) {
        if (c < nChunks) {
            const float* Ab = Abase + ((size_t)c << 12);
            const float* Bb = Bbase + ((size_t)c << 12);
            const uint32_t sb = sbase + (c % NSTAGE) * STAGE_B;
            #pragma unroll
            for (int i = 0; i < 8; i++) {
                const int idx = i * 256 + tid;
                const int mat = idx >> 10;
                const int unit = idx & 1023;
                const float* src = (mat ? Bb : Ab) + (unit << 2);
                cp_async16(sb + mat * 16384 + (unit << 4), src);
            }
        }
        CP_COMMIT();
    };

    issue(0); issue(1); issue(2);

    for (int c = 0; c < nChunks; ++c) {
        CP_WAIT2();
        __syncthreads();
        const uint32_t sA = sbase + (c % NSTAGE) * STAGE_B;
        const uint32_t sB = sA + 16384;

        #pragma unroll
        for (int step = 0; step < 4; ++step) {
            uint32_t Ar[4][4];
            uint32_t Bw[2][4];
            #pragma unroll
            for (int mf = 0; mf < 4; mf++) {
                const uint32_t addr = sA + (((((step * 4 + mf) * 2 + wr) * 32) + lane) << 4);
                LDS128(Ar[mf][0], Ar[mf][1], Ar[mf][2], Ar[mf][3], addr);
            }
            #pragma unroll
            for (int np = 0; np < 2; np++) {
                const uint32_t addr = sB + (((((step * 2 + np) * 4 + wc) * 32) + lane) << 4);
                LDS128(Bw[np][0], Bw[np][1], Bw[np][2], Bw[np][3], addr);
            }
            #pragma unroll
            for (int mf = 0; mf < 4; mf++) {
                #pragma unroll
                for (int nf = 0; nf < 4; nf++) {
                    uint32_t bfrag[2];
                    bfrag[0] = Bw[nf >> 1][(nf & 1) * 2 + 0];
                    bfrag[1] = Bw[nf >> 1][(nf & 1) * 2 + 1];
                    MMA1688(acc[mf][nf], Ar[mf], bfrag);
                }
            }
        }
        __syncthreads();
        issue(c + NSTAGE);
    }

    #pragma unroll
    for (int mf = 0; mf < 4; mf++) {
        const int row = mBase + wr * 64 + mf * 16 + g;
        #pragma unroll
        for (int nf = 0; nf < 4; nf++) {
            const int col = nBase + wc * 32 + nf * 8 + tig * 2;
            float* p0 = &C[(size_t)row * ldc + col];
            float* p1 = &C[(size_t)(row + 8) * ldc + col];
            *(float2*)p0 = make_float2(acc[mf][nf][0], acc[mf][nf][1]);
            *(float2*)p1 = make_float2(acc[mf][nf][2], acc[mf][nf][3]);
        }
    }

    // fused per-column sum / sumsq
    {
        __shared__ float sSum[128], sSq[128];
        if (tid < 128) { sSum[tid] = 0.f; sSq[tid] = 0.f; }
        __syncthreads();
        #pragma unroll
        for (int nf = 0; nf < 4; nf++) {
            #pragma unroll
            for (int b = 0; b < 2; b++) {
                float s = 0.f, q = 0.f;
                #pragma unroll
                for (int mf = 0; mf < 4; mf++) {
                    float v0 = acc[mf][nf][b], v1 = acc[mf][nf][b + 2];
                    s += v0 + v1; q += v0 * v0 + v1 * v1;
                }
                s += __shfl_xor_sync(0xffffffffu, s, 16);
                s += __shfl_xor_sync(0xffffffffu, s, 8);
                s += __shfl_xor_sync(0xffffffffu, s, 4);
                q += __shfl_xor_sync(0xffffffffu, q, 16);
                q += __shfl_xor_sync(0xffffffffu, q, 8);
                q += __shfl_xor_sync(0xffffffffu, q, 4);
                if (g == 0) {
                    const int col = wc * 32 + nf * 8 + tig * 2 + b;
                    atomicAdd(&sSum[col], s);
                    atomicAdd(&sSq[col],  q);
                }
            }
        }
        __syncthreads();
        if (tid < 128) {
            atomicAdd(&stats[nBase + tid],       sSum[tid]);
            atomicAdd(&stats[REP + nBase + tid], sSq[tid]);
        }
    }
}

// ====== GEMM 2: packed A, NATURAL-layout B [K, 896] in smem (fc6 / fc7) ======
constexpr int BSTRIDE_W  = 136;
constexpr int BTILE_NB   = 32 * BSTRIDE_W * 4;         // 17408 B
constexpr int STAGE_NB   = 16384 + BTILE_NB;           // 33792 B
constexpr int NB_SMEM    = NSTAGE * STAGE_NB;          // 101376 B

__global__ __launch_bounds__(256, 2)
void k_mma_gemm_nb(const float* __restrict__ A, const float* __restrict__ B,
                   float* __restrict__ C,
                   int nKC, int ldb, int ldc, int nChunks) {
    extern __shared__ uint32_t sw[];
    const int tid = threadIdx.x;
    const int wid = tid >> 5, lane = tid & 31;
    const int g = lane >> 2, tig = lane & 3;
    const int wr = wid >> 2, wc = wid & 3;
    const int nBase = blockIdx.x * 128;
    const int mBase = blockIdx.y * 128;
    const int chunk0 = blockIdx.z * nChunks;

    float acc[4][4][4];
    #pragma unroll
    for (int i = 0; i < 4; i++)
        #pragma unroll
        for (int j = 0; j < 4; j++)
            #pragma unroll
            for (int v = 0; v < 4; v++) acc[i][j][v] = 0.f;

    const uint32_t sbase = smem_u32(sw);
    const float* Abase = A + (((size_t)(mBase >> 7) * nKC + chunk0) << 12);

    auto issue = [&](int c) {
        if (c < nChunks) {
            const float* Ab = Abase + ((size_t)c << 12);
            const float* Bb = B + (size_t)(chunk0 + c) * 32 * ldb + nBase;
            const uint32_t sb = sbase + (c % NSTAGE) * STAGE_NB;
            #pragma unroll
            for (int i = 0; i < 8; i++) {
                const int idx = i * 256 + tid;
                if (idx < 1024) {                          // A: packed units
                    cp_async16(sb + (idx << 4), Ab + (idx << 2));
                } else {                                   // B: 32 rows x 32 units
                    const int unit = idx - 1024;
                    const int row = unit >> 5, col = unit & 31;
                    cp_async16(sb + 16384 + row * (BSTRIDE_W * 4) + (col << 4),
                               Bb + (size_t)row * ldb + (col << 2));
                }
            }
        }
        CP_COMMIT();
    };

    issue(0); issue(1); issue(2);

    for (int c = 0; c < nChunks; ++c) {
        CP_WAIT2();
        __syncthreads();
        const uint32_t sA = sbase + (c % NSTAGE) * STAGE_NB;
        const uint32_t sB = sA + 16384;

        #pragma unroll
        for (int step = 0; step < 4; ++step) {
            uint32_t Ar[4][4];
            #pragma unroll
            for (int mf = 0; mf < 4; mf++) {
                const uint32_t addr = sA + (((((step * 4 + mf) * 2 + wr) * 32) + lane) << 4);
                LDS128(Ar[mf][0], Ar[mf][1], Ar[mf][2], Ar[mf][3], addr);
            }
            const int kw = step * 8 + tig;
            #pragma unroll
            for (int nf = 0; nf < 4; nf++) {
                const int nloc = wc * 32 + nf * 8 + g;
                uint32_t bfrag[2];
                bfrag[0] = lds_tf32(sB + (kw * BSTRIDE_W + nloc) * 4);
                bfrag[1] = lds_tf32(sB + ((kw + 4) * BSTRIDE_W + nloc) * 4);
                #pragma unroll
                for (int mf = 0; mf < 4; mf++)
                    MMA1688(acc[mf][nf], Ar[mf], bfrag);
            }
        }
        __syncthreads();
        issue(c + NSTAGE);
    }

    #pragma unroll
    for (int mf = 0; mf < 4; mf++) {
        const int row = mBase + wr * 64 + mf * 16 + g;
        #pragma unroll
        for (int nf = 0; nf < 4; nf++) {
            const int col = nBase + wc * 32 + nf * 8 + tig * 2;
            float* p0 = &C[(size_t)row * ldc + col];
            float* p1 = &C[(size_t)(row + 8) * ldc + col];
            atomicAdd(p0,     acc[mf][nf][0]);
            atomicAdd(p0 + 1, acc[mf][nf][1]);
            atomicAdd(p1,     acc[mf][nf][2]);
            atomicAdd(p1 + 1, acc[mf][nf][3]);
        }
    }
}

// ================= glue kernels =================
// tf32 + pack B (conv_w natural [n=r, k])
__global__ void k_cvt(const float* __restrict__ src, float* __restrict__ dst, int total) {
    int i = blockIdx.x * blockDim.x + threadIdx.x;
    if (i < total) {
        const int nn = i / KCONV, k = i % KCONV;
        dst[b_pack_idx(nn, k, 28)] = to_tf32(src[i]);
    }
}

// ROIAlign -> packed A (proven version: grid (49, 1024), 128 threads)
__global__ void k_roi(const float* __restrict__ feat, const float* __restrict__ boxes,
                      const int* __restrict__ bidx, float* __restrict__ A) {
    const int xy = blockIdx.x, n = blockIdx.y, c = threadIdx.x;
    const int qx = xy / RES7, qy = xy % RES7;
    const int m = n * 49 + xy;

    const float x1 = boxes[n*6+0]*PX_SCALE, y1 = boxes[n*6+1]*PX_SCALE,
                z1 = boxes[n*6+2]*PX_SCALE, x2 = boxes[n*6+3]*PX_SCALE,
                y2 = boxes[n*6+4]*PX_SCALE, z2 = boxes[n*6+5]*PX_SCALE;
    const float bx = fmaxf(x2-x1, 1.f) * (1.f/RES7);
    const float by = fmaxf(y2-y1, 1.f) * (1.f/RES7);
    const float bz = fmaxf(z2-z1, 1.f) * (1.f/RES7);
    const float px = x1 + ((float)qx + 0.5f) * bx;
    const float py = y1 + ((float)qy + 0.5f) * by;
    const float fx = floorf(px), lx = px - fx;
    const float fy = floorf(py), ly = py - fy;
    int ix0 = min(max((int)fx, 0), DIMX-1);
    int ix1 = min(max((int)fx + 1, 0), DIMX-1);
    int iy0 = min(max((int)fy, 0), DIMY-1);
    int iy1 = min(max((int)fy + 1, 0), DIMY-1);
    const int b = bidx[n];
    int base[4]; float wxy[4];
    base[0] = ((b*DIMX+ix0)*DIMY+iy0)*DIMZ; wxy[0] = (1.f-lx)*(1.f-ly);
    base[1] = ((b*DIMX+ix0)*DIMY+iy1)*DIMZ; wxy[1] = (1.f-lx)*ly;
    base[2] = ((b*DIMX+ix1)*DIMY+iy0)*DIMZ; wxy[2] = lx*(1.f-ly);
    base[3] = ((b*DIMX+ix1)*DIMY+iy1)*DIMZ; wxy[3] = lx*ly;

    #pragma unroll
    for (int z = 0; z < RES7; z++) {
        const float pz = z1 + ((float)z + 0.5f) * bz;
        const float fz = floorf(pz), lz = pz - fz;
        int iz0 = min(max((int)fz, 0), DIMZ-1);
        int iz1 = min(max((int)fz + 1, 0), DIMZ-1);
        float v = 0.f;
        #pragma unroll
        for (int q = 0; q < 4; q++) {
            float f0 = feat[(size_t)(base[q] + iz0) * C_IN + c];
            float f1 = feat[(size_t)(base[q] + iz1) * C_IN + c];
            v += wxy[q] * ((1.f - lz) * f0 + lz * f1);
        }
        A[a_pack_idx(m, c * RES7 + z, 28)] = to_tf32(v);
    }
}

__global__ void k_finalize(float* __restrict__ stats,
                           float* __restrict__ mean, float* __restrict__ rsig) {
    int r = blockIdx.x * blockDim.x + threadIdx.x;
    if (r < REP) {
        const float inv = 1.0f / (float)MROWS;
        float mu = stats[r] * inv;
        float v  = stats[REP + r] * inv - mu * mu;
        mean[r] = mu;
        rsig[r] = rsqrtf(v + 1e-5f);
        stats[r] = 0.f; stats[REP + r] = 0.f;     // self-clean for next replay
    }
}

// normalize + relu + pack A: Y[n*49+xy, r] -> X2 packed(m=n, k=r*49+xy), nKC=1372
// Y tile fill vectorized to float4 (row segments are 512B contiguous, 16B aligned).
__global__ __launch_bounds__(256) void k_norm(
    const float* __restrict__ Y, float* __restrict__ X2,
    const float* __restrict__ mean, const float* __restrict__ rsig,
    const float* __restrict__ gamma, const float* __restrict__ beta) {
    const int n = blockIdx.x;
    __shared__ float tile[49][132];      // pad to multiple of 4 (stride 132)
    __shared__ float sm[128], sr[128], sg[128], sb[128];
    for (int rc = 0; rc < 7; rc++) {
        const int rbase = rc * 128;
        if (threadIdx.x < 128) {
            int r = rbase + threadIdx.x;
            sm[threadIdx.x] = mean[r];  sr[threadIdx.x] = rsig[r];
            sg[threadIdx.x] = gamma[r]; sb[threadIdx.x] = beta[r];
        }
        // float4 tile fill: 49 rows x 32 float4 = 1568 vector loads
        for (int idx = threadIdx.x; idx < 49 * 32; idx += 256) {
            const int xy = idx >> 5, rq = idx & 31;
            float4 v = *(const float4*)&Y[(size_t)(n * 49 + xy) * REP + rbase + rq * 4];
            *(float4*)&tile[xy][rq * 4] = v;
        }
        __syncthreads();
        for (int o = threadIdx.x; o < 128 * 49; o += 256) {
            int rr = o / 49, xy = o % 49;
            float v = (tile[xy][rr] - sm[rr]) * sr[rr] * sg[rr] + sb[rr];
            X2[a_pack_idx(n, rbase * 49 + o, 1372)] = to_tf32(fmaxf(v, 0.f));
        }
        __syncthreads();
    }
}

// bias + relu + pack A (float4 loads); also self-clean H6
__global__ void k_bias_relu_cvt(float* __restrict__ in, const float* __restrict__ bias,
                                float* __restrict__ dst) {
    int j = blockIdx.x * blockDim.x + threadIdx.x;     // float4 index
    if (j < (NBOX * REP) / 4) {
        const int i = j * 4;
        const int m = i / REP, k = i % REP;            // k is 4-aligned, row-local
        float4 v = *(float4*)&in[i];
        float4 bb = *(const float4*)&bias[k];
        dst[a_pack_idx(m, k + 0, 28)] = to_tf32(fmaxf(v.x + bb.x, 0.f));
        dst[a_pack_idx(m, k + 1, 28)] = to_tf32(fmaxf(v.y + bb.y, 0.f));
        dst[a_pack_idx(m, k + 2, 28)] = to_tf32(fmaxf(v.z + bb.z, 0.f));
        dst[a_pack_idx(m, k + 3, 28)] = to_tf32(fmaxf(v.w + bb.w, 0.f));
        *(float4*)&in[i] = make_float4(0.f, 0.f, 0.f, 0.f);
    }
}

// bias + relu -> out (float4); also self-clean H7
__global__ void k_bias_relu(float* __restrict__ in, const float* __restrict__ bias,
                            float* __restrict__ out) {
    int j = blockIdx.x * blockDim.x + threadIdx.x;
    if (j < (NBOX * REP) / 4) {
        const int i = j * 4;
        const int k = i % REP;
        float4 v = *(float4*)&in[i];
        float4 bb = *(const float4*)&bias[k];
        float4 o;
        o.x = fmaxf(v.x + bb.x, 0.f);
        o.y = fmaxf(v.y + bb.y, 0.f);
        o.z = fmaxf(v.z + bb.z, 0.f);
        o.w = fmaxf(v.w + bb.w, 0.f);
        *(float4*)&out[i] = o;
        *(float4*)&in[i] = make_float4(0.f, 0.f, 0.f, 0.f);
    }
}

// ---------------- launch ----------------
extern "C" void kernel_launch(void* const* d_in, const int* in_sizes, int n_in,
                              void* d_out, int out_size) {
    const float* feat   = (const float*)d_in[0];
    const float* boxes  = (const float*)d_in[1];
    const float* conv_w = (const float*)d_in[2];
    // conv_b (d_in[3]) cancels in the mean subtraction
    const float* gamma  = (const float*)d_in[4];
    const float* beta   = (const float*)d_in[5];
    const float* fc6_w  = (const float*)d_in[6];
    const float* fc6_b  = (const float*)d_in[7];
    const float* fc7_w  = (const float*)d_in[8];
    const float* fc7_b  = (const float*)d_in[9];
    const int*   bidx   = (const int*)d_in[10];
    float* out = (float*)d_out;

    auto sym = [](const void* s) { void* p = nullptr; cudaGetSymbolAddress(&p, s); return p; };
    float* A    = (float*)sym(g_A);
    float* Y    = (float*)sym(g_Y);
    float* X2   = (float*)sym(g_X2);
    float* WC   = (float*)sym(g_WC);
    float* X3   = (float*)sym(g_X3);
    float* H6   = (float*)sym(g_H6);
    float* H7   = (float*)sym(g_H7);
    float* STATS= (float*)sym(g_stats);
    float* MEAN = (float*)sym(g_mean);
    float* RSIG = (float*)sym(g_rsig);

    cudaFuncSetAttribute(k_mma_gemm_conv, cudaFuncAttributeMaxDynamicSharedMemorySize, GEMM_SMEM);
    cudaFuncSetAttribute(k_mma_gemm_nb,   cudaFuncAttributeMaxDynamicSharedMemorySize, NB_SMEM);

    // #1 conv weights (tf32 + pack)
    k_cvt<<<(REP * KCONV + 255) / 256, 256>>>(conv_w, WC, REP * KCONV);
    // #2 ROIAlign -> packed A
    k_roi<<<dim3(49, NBOX), 128>>>(feat, boxes, bidx, A);
    // #3 conv einsum GEMM + fused stats
    k_mma_gemm_conv<<<dim3(7, 392, 1), 256, GEMM_SMEM>>>(
        A, WC, Y, STATS, 28, REP, 28);
    // #4 mean / rsig (+ stats self-clean)
    k_finalize<<<7, 128>>>(STATS, MEAN, RSIG);
    // #5 normalize + relu -> X2 packed (float4 Y reads)
    k_norm<<<NBOX, 256>>>(Y, X2, MEAN, RSIG, gamma, beta);
    // #6 fc6 GEMM, split-K 14, B = fc6_w natural in smem
    k_mma_gemm_nb<<<dim3(7, 8, 14), 256, NB_SMEM>>>(
        X2, fc6_w, H6, 1372, REP, REP, 98);
    // #7 bias+relu -> X3 packed (+ H6 self-clean), float4
    k_bias_relu_cvt<<<896, 256>>>(H6, fc6_b, X3);
    // #8 fc7 GEMM, split-K 4, B = fc7_w natural in smem
    k_mma_gemm_nb<<<dim3(7, 8, 4), 256, NB_SMEM>>>(
        X3, fc7_w, H7, 28, REP, REP, 7);
    // #9 bias + relu -> out (+ H7 self-clean), float4
    k_bias_relu<<<896, 256>>>(H7, fc7_b, out);
}